// round 8
// baseline (speedup 1.0000x reference)
#include <cuda_runtime.h>

// Shapes fixed by the dataset
#define CC  64      // classes
#define AA  256     // feature dim
#define CSPLIT 4    // c-slices per y  -> grid 4*64 = 256 blocks
#define CB  16      // classes per block
#define NT  256     // threads per block (8 warps)
#define TR  8       // a-rows per G tile
#define NTILE (AA / TR)     // 32 tiles
#define NB  (CSPLIT * CC)   // 256 blocks
#define NROW 4096

// Fixed-slot scratch (deterministic, no allocation)
__device__ float g_S[CC * CC];            // S[y][c]
__device__ float g_blockSums[NB];
__device__ unsigned g_sync  = 0;          // epoch grid-sync counter (monotonic)
__device__ unsigned g_done  = 0;          // epoch final-reduction counter
__device__ int   g_lab64;

// ---- Blackwell packed-f32x2 helpers (ptxas never emits FFMA2 from C++) ----
__device__ __forceinline__ unsigned long long pack2(float x) {
    unsigned long long r;
    asm("mov.b64 %0, {%1, %1};" : "=l"(r) : "f"(x));
    return r;
}
__device__ __forceinline__ void fma2(unsigned long long& d,
                                     unsigned long long a,
                                     unsigned long long b) {
    asm("fma.rn.f32x2 %0, %1, %2, %0;" : "+l"(d) : "l"(a), "l"(b));
}
__device__ __forceinline__ float2 unpack2(unsigned long long v) {
    float2 f;
    asm("mov.b64 {%0, %1}, %2;" : "=f"(f.x), "=f"(f.y) : "l"(v));
    return f;
}

// ---------------------------------------------------------------------------
// Single fused kernel:
//   Phase 1: S[y,c] = (w_c - w_y)^T G_y (w_c - w_y), packed-f32x2 math.
//     Block (q,y): 16 c's. Warp w: c = {2w, 2w+1}; lane: b-cols
//     {lane*4..+3, 128+lane*4..+3}.  G_y streamed through a double-buffered
//     smem tile with a SINGLE barrier per tile (STS; bar; LDG-prefetch; compute).
//   epoch grid-sync (256 blocks co-resident: 2/SM, 32KB smem, <=128 regs)
//   Phase 2: softmax-CE over 16 rows per block + fence-counter final mean
// ---------------------------------------------------------------------------
__global__ __launch_bounds__(NT, 2) void k_fused(
        const float* __restrict__ W, const float* __restrict__ CV,
        const float* __restrict__ pred, const void* __restrict__ labels,
        const float* __restrict__ Lam, float* __restrict__ out) {
    __shared__ float Dq[CB][AA];       // 16 KB
    __shared__ float Gt[2][TR * AA];   // 16 KB double buffer
    __shared__ float ws[8];            // phase-2 per-warp sums
    __shared__ unsigned s_flag;

    const int y    = blockIdx.y;
    const int q    = blockIdx.x;
    const int tid  = threadIdx.x;
    const int w    = tid >> 5;
    const int lane = tid & 31;
    const int bid  = y * CSPLIT + q;

    // Labels may be int32 (JAX default) or int64 (x64). Range-check the first
    // 8 int64 interpretations: int32 data aliases high words, blows the range.
    if (bid == 0 && tid == 0) {
        int ok = 1;
#pragma unroll
        for (int i = 0; i < 8; i++) {
            long long v = ((const long long*)labels)[i];
            if (v < 0 || v >= CC) ok = 0;
        }
        g_lab64 = ok;
    }

    // ---- Phase 1: quadratic forms -------------------------------------
    // Build Dq = W[q*16 + r][:] - W[y][:]
    const float* wy = W + y * AA;
    for (int idx = tid; idx < CB * (AA / 4); idx += NT) {
        const int r  = idx >> 6;           // / (AA/4)
        const int a4 = (idx & 63) << 2;
        float4 wv = *(const float4*)(W + (q * CB + r) * AA + a4);
        float4 yv = *(const float4*)(wy + a4);
        float4 d;
        d.x = wv.x - yv.x; d.y = wv.y - yv.y;
        d.z = wv.z - yv.z; d.w = wv.w - yv.w;
        *(float4*)(&Dq[r][a4]) = d;
    }

    const float* G = CV + (size_t)y * (AA * AA);

    // Preload tile 0 into registers (dense: 2 float4 per thread)
    float4 pf0 = *(const float4*)(G + tid * 4);
    float4 pf1 = *(const float4*)(G + 1024 + tid * 4);

    const int c0 = w * 2;                 // this warp's two local c's
    const int b0 = lane * 4;              // first 4 b-cols
    const int b1 = 128 + lane * 4;        // second 4 b-cols

    unsigned long long acc[2][4];
#pragma unroll
    for (int ci = 0; ci < 2; ci++)
#pragma unroll
        for (int k = 0; k < 4; k++) acc[ci][k] = 0ull;

#pragma unroll 1
    for (int t = 0; t < NTILE; t++) {
        // STS tile t (registers -> smem buffer t&1)
        float* nbuf = Gt[t & 1];
        *(float4*)(&nbuf[tid * 4])        = pf0;
        *(float4*)(&nbuf[1024 + tid * 4]) = pf1;
        __syncthreads();   // single barrier per tile (see safety note above)

        if (t + 1 < NTILE) {   // prefetch tile t+1 (overlaps compute below)
            const float* Gn = G + (size_t)(t + 1) * (TR * AA);
            pf0 = *(const float4*)(Gn + tid * 4);
            pf1 = *(const float4*)(Gn + 1024 + tid * 4);
        }

        const float* buf = Gt[t & 1];
        const int abase = t * TR;
#pragma unroll
        for (int rr = 0; rr < TR; rr += 4) {
            float4 u0 = *(const float4*)(&Dq[c0][abase + rr]);       // bcast
            float4 u1 = *(const float4*)(&Dq[c0 + 1][abase + rr]);   // bcast
#pragma unroll
            for (int e = 0; e < 4; e++) {
                const float* row = buf + (rr + e) * AA;
                ulonglong2 ga = *(const ulonglong2*)(row + b0);  // 2x f32x2
                ulonglong2 gb = *(const ulonglong2*)(row + b1);
                const float ue0 = (e == 0) ? u0.x : (e == 1) ? u0.y :
                                  (e == 2) ? u0.z : u0.w;
                const float ue1 = (e == 0) ? u1.x : (e == 1) ? u1.y :
                                  (e == 2) ? u1.z : u1.w;
                unsigned long long ua = pack2(ue0);
                unsigned long long ub = pack2(ue1);
                fma2(acc[0][0], ua, ga.x);
                fma2(acc[0][1], ua, ga.y);
                fma2(acc[0][2], ua, gb.x);
                fma2(acc[0][3], ua, gb.y);
                fma2(acc[1][0], ub, ga.x);
                fma2(acc[1][1], ub, ga.y);
                fma2(acc[1][2], ub, gb.x);
                fma2(acc[1][3], ub, gb.y);
            }
        }
    }

    // Epilogue: S[c] = sum_b t[c,b] * D[c,b]; each warp covers full b-range.
#pragma unroll
    for (int ci = 0; ci < 2; ci++) {
        float4 d0 = *(const float4*)(&Dq[c0 + ci][b0]);
        float4 d1 = *(const float4*)(&Dq[c0 + ci][b1]);
        float2 a0 = unpack2(acc[ci][0]);
        float2 a1 = unpack2(acc[ci][1]);
        float2 a2 = unpack2(acc[ci][2]);
        float2 a3 = unpack2(acc[ci][3]);
        float p = a0.x * d0.x + a0.y * d0.y + a1.x * d0.z + a1.y * d0.w
                + a2.x * d1.x + a2.y * d1.y + a3.x * d1.z + a3.y * d1.w;
#pragma unroll
        for (int off = 16; off; off >>= 1)
            p += __shfl_xor_sync(0xffffffffu, p, off);
        if (lane == 0)
            g_S[y * CC + q * CB + c0 + ci] = p;
    }

    // ---- Epoch grid-sync (monotonic counter; graph-replay safe).
    // All 256 blocks co-resident (2/SM guaranteed by launch bounds).
    __syncthreads();
    if (tid == 0) {
        __threadfence();
        unsigned old = atomicAdd(&g_sync, 1u);
        unsigned target = (old / NB + 1u) * NB;
        while (*(volatile unsigned*)&g_sync < target) { }
        __threadfence();
    }
    __syncthreads();

    // ---- Phase 2: softmax-CE over rows [bid*16, bid*16+16) -------------
    const int   lab64 = g_lab64;
    const float lam   = 0.5f * __ldg(Lam);

    float wsum = 0.f;
#pragma unroll
    for (int rr = 0; rr < 2; rr++) {
        const int n = bid * 16 + w * 2 + rr;
        const int yl = lab64 ? (int)((const long long*)labels)[n]
                             : ((const int*)labels)[n];
        const float* p = pred + (size_t)n * CC;
        const int c2 = lane + 32;

        float a1 = p[lane] + lam * g_S[yl * CC + lane];
        float a2 = p[c2]   + lam * g_S[yl * CC + c2];

        float m = fmaxf(a1, a2);
#pragma unroll
        for (int off = 16; off; off >>= 1)
            m = fmaxf(m, __shfl_xor_sync(0xffffffffu, m, off));
        float e = __expf(a1 - m) + __expf(a2 - m);
#pragma unroll
        for (int off = 16; off; off >>= 1)
            e += __shfl_xor_sync(0xffffffffu, e, off);
        // y is warp-uniform: fetch a_y with a single shuffle, no reduction
        float ay = __shfl_sync(0xffffffffu, (yl < 32) ? a1 : a2, yl & 31);
        wsum += m + __logf(e) - ay;
    }

    if (lane == 0) ws[w] = wsum;
    __syncthreads();
    if (tid == 0) {
        float s = 0.f;
#pragma unroll
        for (int i = 0; i < 8; i++) s += ws[i];
        g_blockSums[bid] = s;
        __threadfence();
        unsigned old = atomicAdd(&g_done, 1u);
        s_flag = ((old % NB) == NB - 1u) ? 1u : 0u;
    }
    __syncthreads();

    // Last-arriving block: deterministic fixed-order sum of 256 partials
    if (s_flag && w == 0) {
        __threadfence();
        float v = 0.f;
#pragma unroll
        for (int k = 0; k < NB / 32; k++)
            v += g_blockSums[k * 32 + lane];
#pragma unroll
        for (int off = 16; off; off >>= 1)
            v += __shfl_xor_sync(0xffffffffu, v, off);
        if (lane == 0)
            out[0] = v / (float)NROW;
    }
}

// ---------------------------------------------------------------------------
// Inputs (metadata order): fc_weight[C,A] f32, features (unused), pred[N,C] f32,
// labels[N] i32/i64, Lambda[1] f32, covariance_sample[C,A,A] f32.
// ---------------------------------------------------------------------------
extern "C" void kernel_launch(void* const* d_in, const int* in_sizes, int n_in,
                              void* d_out, int out_size) {
    const float* W      = (const float*)d_in[0];
    const float* pred   = (const float*)d_in[2];
    const void*  labels = d_in[3];
    const float* Lam    = (const float*)d_in[4];
    const float* CV     = (const float*)d_in[5];

    k_fused<<<dim3(CSPLIT, CC), NT>>>(W, CV, pred, labels, Lam, (float*)d_out);
}

// round 10
// speedup vs baseline: 1.2877x; 1.2877x over previous
#include <cuda_runtime.h>
#include <cstdint>

// Shapes fixed by the dataset
#define CC   64       // classes
#define AA   256      // feature dim
#define NBK  64       // one block per y
#define NT   256      // 8 warps
#define KT   16       // k-tile width (floats)
#define NKT  (AA / KT)   // 16 tiles
#define NROW 4096

#define DS_STRIDE 260    // (4c+k)&31 -> conflict-free A-fragment reads
#define GS_STRIDE 20     // (20n+k)&31 -> conflict-free B-fragment reads
#define GS_BUF    (AA * GS_STRIDE)   // 5120 floats per buffer
#define EPI_STRIDE 66

// Fixed-slot scratch (deterministic, no allocation)
__device__ float g_S[CC * CC];          // S[y][c]
__device__ float g_blockSums[NBK];
__device__ unsigned g_sync = 0;         // epoch grid-sync counter (monotonic)
__device__ unsigned g_done = 0;         // epoch final-reduction counter
__device__ int g_lab64;

// m16n8k8 tf32 MMA (baseline PTX, works on plain sm_103 target)
__device__ __forceinline__ void mma_tf32(float* d,
        uint32_t a0, uint32_t a1, uint32_t a2, uint32_t a3,
        uint32_t b0, uint32_t b1) {
    asm volatile(
        "mma.sync.aligned.m16n8k8.row.col.f32.tf32.tf32.f32 "
        "{%0,%1,%2,%3}, {%4,%5,%6,%7}, {%8,%9}, {%0,%1,%2,%3};"
        : "+f"(d[0]), "+f"(d[1]), "+f"(d[2]), "+f"(d[3])
        : "r"(a0), "r"(a1), "r"(a2), "r"(a3), "r"(b0), "r"(b1));
}

// ---------------------------------------------------------------------------
// Block y: T[c,b] = sum_a D[c,a] G_y[a,b] on tensor cores (tf32), then
// S[y,c] = sum_b T[c,b] D[c,b].  Grid-sync; softmax-CE over 64 rows; mean.
// ---------------------------------------------------------------------------
extern "C" __global__ void __launch_bounds__(NT) k_fused(
        const float* __restrict__ W, const float* __restrict__ CV,
        const float* __restrict__ pred, const void* __restrict__ labels,
        const float* __restrict__ Lam, float* __restrict__ out) {
    extern __shared__ float sm[];
    float* Dsf = sm;                          // [64][260] fp32 D
    float* Gs  = sm + CC * DS_STRIDE;         // 2 x [256][20] G k-tiles
    float* epi = Gs + 2 * GS_BUF;             // [8][66] warp partials
    __shared__ float ws[8];
    __shared__ unsigned s_flag;

    const int y    = blockIdx.x;
    const int tid  = threadIdx.x;
    const int w    = tid >> 5;
    const int lane = tid & 31;
    const int g    = lane >> 2;   // fragment groupID
    const int t    = lane & 3;    // fragment threadID_in_group

    // Labels may be int32 (JAX default) or int64 (x64): range-check 8 int64
    // interpretations; int32 data aliases high words and blows the range.
    if (y == 0 && tid == 0) {
        int ok = 1;
#pragma unroll
        for (int i = 0; i < 8; i++) {
            long long v = ((const long long*)labels)[i];
            if (v < 0 || v >= CC) ok = 0;
        }
        g_lab64 = ok;
    }

    // ---- Build D = W - w_y in smem (fp32, padded stride) ---------------
    const float* wy = W + y * AA;
    for (int i = tid; i < CC * (AA / 4); i += NT) {
        const int c  = i >> 6;
        const int a4 = (i & 63) << 2;
        float4 wv = *(const float4*)(W + c * AA + a4);
        float4 yv = *(const float4*)(wy + a4);
        float4 d;
        d.x = wv.x - yv.x; d.y = wv.y - yv.y;
        d.z = wv.z - yv.z; d.w = wv.w - yv.w;
        *(float4*)(&Dsf[c * DS_STRIDE + a4]) = d;
    }

    const float* G = CV + (size_t)y * (AA * AA);

    // Tile loader mapping: thread covers 4 float4: row = i*64 + (tid>>2),
    // seg = tid&3  (64B per row per tile; lanes cover 8 rows x 4 segs)
    const int lrow = tid >> 2;    // 0..63 base row
    const int lseg = (tid & 3) << 2;

    // Preload tile 0
    {
#pragma unroll
        for (int i = 0; i < 4; i++) {
            const int row = i * 64 + lrow;
            float4 v = *(const float4*)(G + row * AA + lseg);
            *(float4*)(&Gs[row * GS_STRIDE + lseg]) = v;
        }
    }
    __syncthreads();

    float acc[4][4][4];   // [mtile][ntile][reg]
#pragma unroll
    for (int mt = 0; mt < 4; mt++)
#pragma unroll
        for (int nt = 0; nt < 4; nt++)
#pragma unroll
            for (int r = 0; r < 4; r++) acc[mt][nt][r] = 0.f;

#pragma unroll 1
    for (int kt = 0; kt < NKT; kt++) {
        float4 pf[4];
        if (kt + 1 < NKT) {     // prefetch next k-tile into registers
            const float* Gn = G + (kt + 1) * KT;
#pragma unroll
            for (int i = 0; i < 4; i++)
                pf[i] = *(const float4*)(Gn + (i * 64 + lrow) * AA + lseg);
        }
        const float* buf = Gs + (kt & 1) * GS_BUF;

#pragma unroll
        for (int ks = 0; ks < 2; ks++) {
            const int kg = kt * KT + ks * 8;   // global k (A)
            const int kl = ks * 8;             // local k (B tile)

            uint32_t af[4][4];
#pragma unroll
            for (int mt = 0; mt < 4; mt++) {
                const int c0 = mt * 16 + g;
                af[mt][0] = __float_as_uint(Dsf[c0 * DS_STRIDE + kg + t]);
                af[mt][1] = __float_as_uint(Dsf[(c0 + 8) * DS_STRIDE + kg + t]);
                af[mt][2] = __float_as_uint(Dsf[c0 * DS_STRIDE + kg + t + 4]);
                af[mt][3] = __float_as_uint(Dsf[(c0 + 8) * DS_STRIDE + kg + t + 4]);
            }
            uint32_t bf[4][2];
#pragma unroll
            for (int nt = 0; nt < 4; nt++) {
                const int n = w * 32 + nt * 8 + g;
                bf[nt][0] = __float_as_uint(buf[n * GS_STRIDE + kl + t]);
                bf[nt][1] = __float_as_uint(buf[n * GS_STRIDE + kl + t + 4]);
            }
#pragma unroll
            for (int mt = 0; mt < 4; mt++)
#pragma unroll
                for (int nt = 0; nt < 4; nt++)
                    mma_tf32(acc[mt][nt], af[mt][0], af[mt][1], af[mt][2],
                             af[mt][3], bf[nt][0], bf[nt][1]);
        }

        if (kt + 1 < NKT) {
            __syncthreads();   // all warps done reading the buffer we overwrite
            float* nbuf = Gs + ((kt + 1) & 1) * GS_BUF;
#pragma unroll
            for (int i = 0; i < 4; i++)
                *(float4*)(&nbuf[(i * 64 + lrow) * GS_STRIDE + lseg]) = pf[i];
            __syncthreads();
        }
    }

    // ---- Epilogue: S[c] = sum_b T[c,b] * D[c,b] ------------------------
    // acc reg layout: [0]=(c0, b0) [1]=(c0, b0+1) [2]=(c0+8, b0) [3]=(c0+8, b0+1)
    // with c0 = mt*16+g, b0 = w*32 + nt*8 + 2t.
#pragma unroll
    for (int mt = 0; mt < 4; mt++) {
        const int c0 = mt * 16 + g;
        const int c1 = c0 + 8;
        float s0 = 0.f, s1 = 0.f;
#pragma unroll
        for (int nt = 0; nt < 4; nt++) {
            const int b = w * 32 + nt * 8 + 2 * t;
            s0 += acc[mt][nt][0] * Dsf[c0 * DS_STRIDE + b]
                + acc[mt][nt][1] * Dsf[c0 * DS_STRIDE + b + 1];
            s1 += acc[mt][nt][2] * Dsf[c1 * DS_STRIDE + b]
                + acc[mt][nt][3] * Dsf[c1 * DS_STRIDE + b + 1];
        }
        s0 += __shfl_xor_sync(0xffffffffu, s0, 1);
        s0 += __shfl_xor_sync(0xffffffffu, s0, 2);
        s1 += __shfl_xor_sync(0xffffffffu, s1, 1);
        s1 += __shfl_xor_sync(0xffffffffu, s1, 2);
        if (t == 0) {
            epi[w * EPI_STRIDE + c0] = s0;
            epi[w * EPI_STRIDE + c1] = s1;
        }
    }
    __syncthreads();
    if (tid < CC) {   // combine the 8 warps' disjoint b-ranges (fixed order)
        float s = 0.f;
#pragma unroll
        for (int ww = 0; ww < 8; ww++) s += epi[ww * EPI_STRIDE + tid];
        g_S[y * CC + tid] = s;
    }

    // ---- Epoch grid-sync (monotonic; 64 blocks all co-resident) --------
    __syncthreads();
    if (tid == 0) {
        __threadfence();
        unsigned old = atomicAdd(&g_sync, 1u);
        unsigned target = (old / NBK + 1u) * NBK;
        while (*(volatile unsigned*)&g_sync < target) { }
        __threadfence();
    }
    __syncthreads();

    // ---- Phase 2: softmax-CE over rows [y*64, y*64+64) -----------------
    const int   lab64 = g_lab64;
    const float lam   = 0.5f * __ldg(Lam);

    float wsum = 0.f;
#pragma unroll
    for (int rr = 0; rr < 8; rr++) {
        const int n = y * 64 + w * 8 + rr;
        const int yl = lab64 ? (int)((const long long*)labels)[n]
                             : ((const int*)labels)[n];
        const float* p = pred + (size_t)n * CC;
        const int c2 = lane + 32;

        float a1 = p[lane] + lam * g_S[yl * CC + lane];
        float a2 = p[c2]   + lam * g_S[yl * CC + c2];

        float m = fmaxf(a1, a2);
#pragma unroll
        for (int off = 16; off; off >>= 1)
            m = fmaxf(m, __shfl_xor_sync(0xffffffffu, m, off));
        float e = __expf(a1 - m) + __expf(a2 - m);
#pragma unroll
        for (int off = 16; off; off >>= 1)
            e += __shfl_xor_sync(0xffffffffu, e, off);
        float ay = __shfl_sync(0xffffffffu, (yl < 32) ? a1 : a2, yl & 31);
        wsum += m + __logf(e) - ay;
    }

    if (lane == 0) ws[w] = wsum;
    __syncthreads();
    if (tid == 0) {
        float s = 0.f;
#pragma unroll
        for (int i = 0; i < 8; i++) s += ws[i];
        g_blockSums[y] = s;
        __threadfence();
        unsigned old = atomicAdd(&g_done, 1u);
        s_flag = ((old % NBK) == NBK - 1u) ? 1u : 0u;
    }
    __syncthreads();

    if (s_flag && w == 0) {   // last block: fixed-order sum of 64 partials
        __threadfence();
        float v = g_blockSums[lane] + g_blockSums[lane + 32];
#pragma unroll
        for (int off = 16; off; off >>= 1)
            v += __shfl_xor_sync(0xffffffffu, v, off);
        if (lane == 0)
            out[0] = v / (float)NROW;
    }
}

// ---------------------------------------------------------------------------
// Inputs (metadata order): fc_weight[C,A] f32, features (unused), pred[N,C] f32,
// labels[N] i32/i64, Lambda[1] f32, covariance_sample[C,A,A] f32.
// ---------------------------------------------------------------------------
extern "C" void kernel_launch(void* const* d_in, const int* in_sizes, int n_in,
                              void* d_out, int out_size) {
    const float* W      = (const float*)d_in[0];
    const float* pred   = (const float*)d_in[2];
    const void*  labels = d_in[3];
    const float* Lam    = (const float*)d_in[4];
    const float* CV     = (const float*)d_in[5];

    const int smem_bytes = (CC * DS_STRIDE + 2 * GS_BUF + 8 * EPI_STRIDE)
                         * (int)sizeof(float);   // ~109.6 KB
    cudaFuncSetAttribute(k_fused, cudaFuncAttributeMaxDynamicSharedMemorySize,
                         smem_bytes);
    k_fused<<<NBK, NT, smem_bytes>>>(W, CV, pred, labels, Lam, (float*)d_out);
}

// round 12
// speedup vs baseline: 2.0541x; 1.5951x over previous
#include <cuda_runtime.h>
#include <cstdint>

// Shapes fixed by the dataset
#define CC   64       // classes
#define AA   256      // feature dim
#define NBK  128      // blocks: (b-half, y)
#define NT   256      // 8 warps
#define NROW 4096

#define DST 260       // D row stride: (4c+k)&31 conflict-free fragment reads
#define GST 260       // G row stride: same argument
#define EPI_STRIDE 66

// Fixed-slot scratch (deterministic, no allocation)
__device__ float g_Sh[2 * CC * CC];     // S half-sums [h][y][c]
__device__ float g_blockSums[NBK];
__device__ unsigned g_sync = 0;         // epoch grid-sync counter (monotonic)
__device__ unsigned g_done = 0;         // epoch final-reduction counter
__device__ int g_lab64;

// m16n8k8 tf32 MMA (baseline PTX, compiles for plain sm_103 target)
__device__ __forceinline__ void mma_tf32(float* d,
        uint32_t a0, uint32_t a1, uint32_t a2, uint32_t a3,
        uint32_t b0, uint32_t b1) {
    asm volatile(
        "mma.sync.aligned.m16n8k8.row.col.f32.tf32.tf32.f32 "
        "{%0,%1,%2,%3}, {%4,%5,%6,%7}, {%8,%9}, {%0,%1,%2,%3};"
        : "+f"(d[0]), "+f"(d[1]), "+f"(d[2]), "+f"(d[3])
        : "r"(a0), "r"(a1), "r"(a2), "r"(a3), "r"(b0), "r"(b1));
}

// ---------------------------------------------------------------------------
// Block (h, y): T[c,b] = sum_a D[c,a] G_y[a,b] for b in [h*128, h*128+128),
// via m16n8k8 tf32.  B cols are G rows (symmetry) -> load G-half + D into
// smem once, 1 barrier, then a barrier-free 32-step MMA loop.
// S_half[h][y][c] = sum_b T[c,b] D[c,b].  Grid-sync; CE over 32 rows; mean.
// ---------------------------------------------------------------------------
extern "C" __global__ void __launch_bounds__(NT) k_fused(
        const float* __restrict__ W, const float* __restrict__ CV,
        const float* __restrict__ pred, const void* __restrict__ labels,
        const float* __restrict__ Lam, float* __restrict__ out) {
    extern __shared__ float sm[];
    float* Dsf = sm;                       // [64][260]  D = W - w_y
    float* Gs  = sm + CC * DST;            // [128][260] G rows h*128..+127
    float* epi = Gs + 128 * GST;           // [8][66] warp partials
    __shared__ float ws[8];
    __shared__ unsigned s_flag;

    const int h    = blockIdx.x;
    const int y    = blockIdx.y;
    const int tid  = threadIdx.x;
    const int w    = tid >> 5;
    const int lane = tid & 31;
    const int g    = lane >> 2;   // fragment groupID
    const int t    = lane & 3;    // fragment threadID_in_group
    const int bid  = y * 2 + h;

    // Labels may be int32 (JAX default) or int64 (x64): range-check 8 int64
    // interpretations; int32 data aliases high words and blows the range.
    if (bid == 0 && tid == 0) {
        int ok = 1;
#pragma unroll
        for (int i = 0; i < 8; i++) {
            long long v = ((const long long*)labels)[i];
            if (v < 0 || v >= CC) ok = 0;
        }
        g_lab64 = ok;
    }

    // ---- Bulk load: D (64x256) and G-half (128x256), high MLP ----------
    const float* wy = W + y * AA;
    for (int i = tid; i < CC * (AA / 4); i += NT) {
        const int c  = i >> 6;
        const int a4 = (i & 63) << 2;
        float4 wv = *(const float4*)(W + c * AA + a4);
        float4 yv = *(const float4*)(wy + a4);
        float4 d;
        d.x = wv.x - yv.x; d.y = wv.y - yv.y;
        d.z = wv.z - yv.z; d.w = wv.w - yv.w;
        *(float4*)(&Dsf[c * DST + a4]) = d;
    }
    const float* G = CV + (size_t)y * (AA * AA) + (size_t)h * 128 * AA;
    for (int i = tid; i < 128 * (AA / 4); i += NT) {
        const int r   = i >> 6;
        const int seg = (i & 63) << 2;
        float4 v = *(const float4*)(G + r * AA + seg);
        *(float4*)(&Gs[r * GST + seg]) = v;
    }
    __syncthreads();   // the only barrier before the epilogue

    // ---- Barrier-free MMA loop: warp w = mt-pair (w&1)*2 x nt-quad (w>>1)*4
    const int mtb = (w & 1) * 2;
    const int ntb = (w >> 1) * 4;

    float acc[2][4][4];
#pragma unroll
    for (int mi = 0; mi < 2; mi++)
#pragma unroll
        for (int ni = 0; ni < 4; ni++)
#pragma unroll
            for (int r = 0; r < 4; r++) acc[mi][ni][r] = 0.f;

#pragma unroll 4
    for (int ks = 0; ks < 32; ks++) {
        const int kg = ks * 8;
        uint32_t af[2][4];
#pragma unroll
        for (int mi = 0; mi < 2; mi++) {
            const int c0 = (mtb + mi) * 16 + g;
            af[mi][0] = __float_as_uint(Dsf[c0 * DST + kg + t]);
            af[mi][1] = __float_as_uint(Dsf[(c0 + 8) * DST + kg + t]);
            af[mi][2] = __float_as_uint(Dsf[c0 * DST + kg + t + 4]);
            af[mi][3] = __float_as_uint(Dsf[(c0 + 8) * DST + kg + t + 4]);
        }
        uint32_t bf[4][2];
#pragma unroll
        for (int ni = 0; ni < 4; ni++) {
            const int n = (ntb + ni) * 8 + g;
            bf[ni][0] = __float_as_uint(Gs[n * GST + kg + t]);
            bf[ni][1] = __float_as_uint(Gs[n * GST + kg + t + 4]);
        }
#pragma unroll
        for (int mi = 0; mi < 2; mi++)
#pragma unroll
            for (int ni = 0; ni < 4; ni++)
                mma_tf32(acc[mi][ni], af[mi][0], af[mi][1], af[mi][2],
                         af[mi][3], bf[ni][0], bf[ni][1]);
    }

    // ---- Epilogue: S_half[c] = sum_b T[c,b] * D[c, h*128+b] -------------
    // acc regs: [0]=(c0,b0) [1]=(c0,b0+1) [2]=(c0+8,b0) [3]=(c0+8,b0+1),
    // c0 = mt*16+g, b0 = nt*8 + 2t  (b global = h*128 + b0).
#pragma unroll
    for (int mi = 0; mi < 2; mi++) {
        const int c0 = (mtb + mi) * 16 + g;
        const int c1 = c0 + 8;
        float s0 = 0.f, s1 = 0.f;
#pragma unroll
        for (int ni = 0; ni < 4; ni++) {
            const int bg = h * 128 + (ntb + ni) * 8 + 2 * t;
            s0 += acc[mi][ni][0] * Dsf[c0 * DST + bg]
                + acc[mi][ni][1] * Dsf[c0 * DST + bg + 1];
            s1 += acc[mi][ni][2] * Dsf[c1 * DST + bg]
                + acc[mi][ni][3] * Dsf[c1 * DST + bg + 1];
        }
        s0 += __shfl_xor_sync(0xffffffffu, s0, 1);
        s0 += __shfl_xor_sync(0xffffffffu, s0, 2);
        s1 += __shfl_xor_sync(0xffffffffu, s1, 1);
        s1 += __shfl_xor_sync(0xffffffffu, s1, 2);
        if (t == 0) {
            epi[w * EPI_STRIDE + c0] = s0;
            epi[w * EPI_STRIDE + c1] = s1;
        }
    }
    __syncthreads();
    if (tid < CC) {   // combine warps of matching c-parity (fixed order)
        const int par = tid >> 5;   // c<32 -> even warps, c>=32 -> odd warps
        float s = 0.f;
#pragma unroll
        for (int j = 0; j < 4; j++)
            s += epi[(2 * j + par) * EPI_STRIDE + tid];
        g_Sh[(h * CC + y) * CC + tid] = s;
    }

    // ---- Epoch grid-sync (monotonic; 128 blocks all co-resident @1/SM) --
    __syncthreads();
    if (tid == 0) {
        __threadfence();
        unsigned old = atomicAdd(&g_sync, 1u);
        unsigned target = (old / NBK + 1u) * NBK;
        while (*(volatile unsigned*)&g_sync < target) { }
        __threadfence();
    }
    __syncthreads();

    // ---- Phase 2: softmax-CE over rows [bid*32, bid*32+32) --------------
    const int   lab64 = g_lab64;
    const float lam   = 0.5f * __ldg(Lam);
    const float* S0 = g_Sh;               // h = 0 halves
    const float* S1 = g_Sh + CC * CC;     // h = 1 halves

    float wsum = 0.f;
#pragma unroll
    for (int rr = 0; rr < 4; rr++) {
        const int n = bid * 32 + w * 4 + rr;
        const int yl = lab64 ? (int)((const long long*)labels)[n]
                             : ((const int*)labels)[n];
        const float* p = pred + (size_t)n * CC;
        const int c2 = lane + 32;

        float a1 = p[lane] + lam * (S0[yl * CC + lane] + S1[yl * CC + lane]);
        float a2 = p[c2]   + lam * (S0[yl * CC + c2]   + S1[yl * CC + c2]);

        float m = fmaxf(a1, a2);
#pragma unroll
        for (int off = 16; off; off >>= 1)
            m = fmaxf(m, __shfl_xor_sync(0xffffffffu, m, off));
        float e = __expf(a1 - m) + __expf(a2 - m);
#pragma unroll
        for (int off = 16; off; off >>= 1)
            e += __shfl_xor_sync(0xffffffffu, e, off);
        float ay = __shfl_sync(0xffffffffu, (yl < 32) ? a1 : a2, yl & 31);
        wsum += m + __logf(e) - ay;
    }

    if (lane == 0) ws[w] = wsum;
    __syncthreads();
    if (tid == 0) {
        float s = 0.f;
#pragma unroll
        for (int i = 0; i < 8; i++) s += ws[i];
        g_blockSums[bid] = s;
        __threadfence();
        unsigned old = atomicAdd(&g_done, 1u);
        s_flag = ((old % NBK) == NBK - 1u) ? 1u : 0u;
    }
    __syncthreads();

    if (s_flag && w == 0) {   // last block: fixed-order sum of 128 partials
        __threadfence();
        float v = 0.f;
#pragma unroll
        for (int k = 0; k < NBK / 32; k++)
            v += g_blockSums[k * 32 + lane];
#pragma unroll
        for (int off = 16; off; off >>= 1)
            v += __shfl_xor_sync(0xffffffffu, v, off);
        if (lane == 0)
            out[0] = v / (float)NROW;
    }
}

// ---------------------------------------------------------------------------
// Inputs (metadata order): fc_weight[C,A] f32, features (unused), pred[N,C] f32,
// labels[N] i32/i64, Lambda[1] f32, covariance_sample[C,A,A] f32.
// ---------------------------------------------------------------------------
extern "C" void kernel_launch(void* const* d_in, const int* in_sizes, int n_in,
                              void* d_out, int out_size) {
    const float* W      = (const float*)d_in[0];
    const float* pred   = (const float*)d_in[2];
    const void*  labels = d_in[3];
    const float* Lam    = (const float*)d_in[4];
    const float* CV     = (const float*)d_in[5];

    const int smem_bytes = (CC * DST + 128 * GST + 8 * EPI_STRIDE)
                         * (int)sizeof(float);   // ~197 KB
    cudaFuncSetAttribute(k_fused, cudaFuncAttributeMaxDynamicSharedMemorySize,
                         smem_bytes);
    k_fused<<<dim3(2, CC), NT, smem_bytes>>>(W, CV, pred, labels, Lam,
                                             (float*)d_out);
}